// round 13
// baseline (speedup 1.0000x reference)
#include <cuda_runtime.h>
#include <cstdint>
#include <cstddef>

// Ridge_51178830299316 — dual formulation + panel lookahead, round 13.
//
// pred = y - u_final from one fused Cholesky/forward-sub of A = X X^T + I per
// batch (leading-block property serves all prefixes). New in this round: the
// panel pipeline. C(k) is split into C1 (next panel's 32-col strip, all
// threads) and C2 (rest). Then warps 0-5 ("solver") run A(k+1) -> named
// barrier -> B(k+1) into LT[cur^1], CONCURRENTLY with warps 6-15 ("update")
// running C2(k) from LT[cur]. Two __syncthreads per panel.

#define NPTS   256
#define DIM    128
#define BATCH  32
#define K2T    512
#define APACK_SIZE 33280   // sum of 4-aligned row lengths

__host__ __device__ __forceinline__ int rowbase(int r) {
    const int q = r >> 2, rem = r & 3;
    return 8 * q * (q - 1) + 4 * rem * q + 4 * r;
}

__device__ float g_gram[BATCH][APACK_SIZE];

// ============================ K1: Gram (unchanged) ========================
__global__ void __launch_bounds__(256) gram_kernel(const float* __restrict__ data)
{
    const int bid = blockIdx.x;
    const int b = bid / 36, t36 = bid % 36;
    int ti = 0;
    while ((ti + 1) * (ti + 2) / 2 <= t36) ++ti;
    const int tj = t36 - ti * (ti + 1) / 2;

    __shared__ float Xi[32][132];
    __shared__ float Xj[32][132];

    const float* Xb = data + (size_t)b * NPTS * DIM;
    const int tid = threadIdx.x;
    for (int q = tid; q < 1024; q += 256) {
        const int r = q >> 5, c4 = q & 31;
        *reinterpret_cast<float4*>(&Xi[r][c4 * 4]) =
            reinterpret_cast<const float4*>(Xb + (size_t)(ti * 32 + r) * DIM)[c4];
        *reinterpret_cast<float4*>(&Xj[r][c4 * 4]) =
            reinterpret_cast<const float4*>(Xb + (size_t)(tj * 32 + r) * DIM)[c4];
    }
    __syncthreads();

    const int ty = tid >> 4, tx = tid & 15;
    const int r0 = 2 * ty, c0 = 2 * tx;
    float a00 = 0.f, a01 = 0.f, a10 = 0.f, a11 = 0.f;
    #pragma unroll 8
    for (int k4 = 0; k4 < 32; ++k4) {
        const float4 xi0 = *reinterpret_cast<const float4*>(&Xi[r0][k4 * 4]);
        const float4 xi1 = *reinterpret_cast<const float4*>(&Xi[r0 + 1][k4 * 4]);
        const float4 xj0 = *reinterpret_cast<const float4*>(&Xj[c0][k4 * 4]);
        const float4 xj1 = *reinterpret_cast<const float4*>(&Xj[c0 + 1][k4 * 4]);
        a00 += xi0.x*xj0.x + xi0.y*xj0.y + xi0.z*xj0.z + xi0.w*xj0.w;
        a01 += xi0.x*xj1.x + xi0.y*xj1.y + xi0.z*xj1.z + xi0.w*xj1.w;
        a10 += xi1.x*xj0.x + xi1.y*xj0.y + xi1.z*xj0.z + xi1.w*xj0.w;
        a11 += xi1.x*xj1.x + xi1.y*xj1.y + xi1.z*xj1.z + xi1.w*xj1.w;
    }
    const int gr0 = ti * 32 + r0, gc0 = tj * 32 + c0;
    float* gg = g_gram[b];
    if (gr0 >= gc0)         gg[rowbase(gr0)     + gc0]     = a00 + (gr0     == gc0     ? 1.f : 0.f);
    if (gr0 >= gc0 + 1)     gg[rowbase(gr0)     + gc0 + 1] = a01 + (gr0     == gc0 + 1 ? 1.f : 0.f);
    if (gr0 + 1 >= gc0)     gg[rowbase(gr0 + 1) + gc0]     = a10 + (gr0 + 1 == gc0     ? 1.f : 0.f);
    if (gr0 + 1 >= gc0 + 1) gg[rowbase(gr0 + 1) + gc0 + 1] = a11 + (gr0 + 1 == gc0 + 1 ? 1.f : 0.f);
}

// ==================== K2: pipelined Cholesky + forward sub ================
struct K2Smem {
    float A[APACK_SIZE];       // packed lower, 4-aligned rows
    float u[NPTS];             // residual y - pred
    float z[32];
    float invD[32];
    float D[32][32];           // current panel diagonal block L
    float LT[2][32][NPTS];     // panel L transposed, double-buffered
    float colbuf[32];
};

__device__ __forceinline__ void phaseA(K2Smem& sm, int kp, int tid)
{
    // warp 0 only (tid < 32)
    const int P = 32 * kp;
    const int rp = tid, gr = P + rp, rb = rowbase(gr);
    float arow[32];
    #pragma unroll
    for (int c = 0; c < 32; ++c) arow[c] = sm.A[rb + P + c];  // c>rp garbage, unused
    float ur = sm.u[gr];
    #pragma unroll
    for (int c = 0; c < 32; ++c) {
        const float d  = __shfl_sync(0xffffffffu, arow[c], c);
        const float uc = __shfl_sync(0xffffffffu, ur, c);
        const float rs = rsqrtf(d);
        const float zc = uc * rs;
        const float lrc = (rp > c) ? arow[c] * rs : 0.f;
        if (rp == c) { arow[c] = d * rs; sm.z[c] = zc; sm.invD[c] = rs; }
        if (rp > c)  { arow[c] = lrc; ur -= lrc * zc; }
        sm.colbuf[rp] = lrc;
        __syncwarp();
        float cb[32];
        #pragma unroll
        for (int q = 0; q < 8; ++q)
            *reinterpret_cast<float4*>(&cb[4 * q]) =
                *reinterpret_cast<const float4*>(&sm.colbuf[4 * q]);
        #pragma unroll
        for (int j = 0; j < 32; ++j)
            if (j > c) arow[j] -= lrc * cb[j];
        __syncwarp();
    }
    sm.u[gr] = ur;
    #pragma unroll
    for (int q = 0; q < 8; ++q)
        *reinterpret_cast<float4*>(&sm.D[rp][4 * q]) =
            *reinterpret_cast<const float4*>(&arow[4 * q]);
}

__device__ __forceinline__ void phaseB(K2Smem& sm, int kp, int buf, int tid)
{
    const int P = 32 * kp;
    const int R = NPTS - P - 32;
    if (tid < R) {
        const int gr = P + 32 + tid, rb = rowbase(gr);
        float Lr[32];
        #pragma unroll
        for (int c = 0; c < 32; ++c) {
            float acc = sm.A[rb + P + c];
            #pragma unroll
            for (int p = 0; p < 32; ++p)
                if (p < c) acc -= Lr[p] * sm.D[c][p];
            Lr[c] = acc * sm.invD[c];
        }
        float du = 0.f;
        #pragma unroll
        for (int c = 0; c < 32; ++c) du += Lr[c] * sm.z[c];
        sm.u[gr] -= du;
        #pragma unroll
        for (int c = 0; c < 32; ++c) sm.LT[buf][c][gr] = Lr[c];
    }
}

__device__ __forceinline__ void phaseC2(K2Smem& sm, int k, int cur, int a0)
{
    const int c0t = 4 * (k + 2);
    const int mrem = 32 - c0t;
    const int Tact = mrem * (mrem + 1) / 2;
    for (int a = a0; a < Tact; a += 320) {
        int t = (int)(0.5f * (__fsqrt_rn(8.f * a + 1.f) - 1.f));
        while ((t + 1) * (t + 2) / 2 <= a) ++t;
        while (t * (t + 1) / 2 > a) --t;
        const int tc = 31 - t;
        const int tr = 31 - (a - t * (t + 1) / 2);
        const int r0 = 8 * tr, cc0 = 8 * tc;

        float acc[8][8];
        int rbs[8];
        #pragma unroll
        for (int i = 0; i < 8; ++i) {
            rbs[i] = rowbase(r0 + i);
            const float4 v0 = *reinterpret_cast<const float4*>(&sm.A[rbs[i] + cc0]);
            const float4 v1 = *reinterpret_cast<const float4*>(&sm.A[rbs[i] + cc0 + 4]);
            acc[i][0] = v0.x; acc[i][1] = v0.y; acc[i][2] = v0.z; acc[i][3] = v0.w;
            acc[i][4] = v1.x; acc[i][5] = v1.y; acc[i][6] = v1.z; acc[i][7] = v1.w;
        }
        #pragma unroll 4
        for (int p = 0; p < 32; ++p) {
            const float4 lr0 = *reinterpret_cast<const float4*>(&sm.LT[cur][p][r0]);
            const float4 lr1 = *reinterpret_cast<const float4*>(&sm.LT[cur][p][r0 + 4]);
            const float4 lc0 = *reinterpret_cast<const float4*>(&sm.LT[cur][p][cc0]);
            const float4 lc1 = *reinterpret_cast<const float4*>(&sm.LT[cur][p][cc0 + 4]);
            const float lr[8] = {lr0.x, lr0.y, lr0.z, lr0.w, lr1.x, lr1.y, lr1.z, lr1.w};
            const float lc[8] = {lc0.x, lc0.y, lc0.z, lc0.w, lc1.x, lc1.y, lc1.z, lc1.w};
            #pragma unroll
            for (int i = 0; i < 8; ++i)
                #pragma unroll
                for (int j = 0; j < 8; ++j)
                    acc[i][j] -= lr[i] * lc[j];
        }
        if (tr != tc) {
            #pragma unroll
            for (int i = 0; i < 8; ++i) {
                *reinterpret_cast<float4*>(&sm.A[rbs[i] + cc0]) =
                    make_float4(acc[i][0], acc[i][1], acc[i][2], acc[i][3]);
                *reinterpret_cast<float4*>(&sm.A[rbs[i] + cc0 + 4]) =
                    make_float4(acc[i][4], acc[i][5], acc[i][6], acc[i][7]);
            }
        } else {
            #pragma unroll
            for (int i = 0; i < 8; ++i)
                #pragma unroll
                for (int j = 0; j < 8; ++j)
                    if (j <= i) sm.A[rbs[i] + cc0 + j] = acc[i][j];
        }
    }
}

__global__ void __launch_bounds__(K2T, 1)
chol_kernel(const float* __restrict__ targets, float* __restrict__ out)
{
    extern __shared__ char smraw[];
    K2Smem& sm = *reinterpret_cast<K2Smem*>(smraw);
    const int b = blockIdx.x, tid = threadIdx.x;

    {
        const float4* src = reinterpret_cast<const float4*>(g_gram[b]);
        float4* dst = reinterpret_cast<float4*>(sm.A);
        for (int i = tid; i < APACK_SIZE / 4; i += K2T) dst[i] = src[i];
    }
    if (tid < NPTS) sm.u[tid] = targets[(size_t)b * NPTS + tid];
    __syncthreads();

    // ---- Prologue: A(0), B(0) -> LT[0] ----
    if (tid < 32) phaseA(sm, 0, tid);
    __syncthreads();
    phaseB(sm, 0, 0, tid);       // internal guard tid < 224
    __syncthreads();

    int cur = 0;
    #pragma unroll 1
    for (int k = 0; k < 7; ++k) {
        const int Pn = 32 * (k + 1);

        // ---- C1: strip cols [Pn, Pn+32), rows [Pn, 256), ALL threads ----
        const int nrows = NPTS - Pn;
        for (int idx = tid; idx < nrows; idx += K2T) {
            const int r = Pn + idx;
            const int rb = rowbase(r);
            float lr[32];
            #pragma unroll
            for (int p = 0; p < 32; ++p) lr[p] = sm.LT[cur][p][r];
            float acc[32];
            #pragma unroll
            for (int j = 0; j < 8; ++j)
                *reinterpret_cast<float4*>(&acc[4 * j]) =
                    *reinterpret_cast<const float4*>(&sm.A[rb + Pn + 4 * j]);
            #pragma unroll 8
            for (int p = 0; p < 32; ++p) {
                #pragma unroll
                for (int j = 0; j < 8; ++j) {
                    const float4 lc =
                        *reinterpret_cast<const float4*>(&sm.LT[cur][p][Pn + 4 * j]);
                    acc[4*j]   -= lr[p] * lc.x;
                    acc[4*j+1] -= lr[p] * lc.y;
                    acc[4*j+2] -= lr[p] * lc.z;
                    acc[4*j+3] -= lr[p] * lc.w;
                }
            }
            if (idx >= 32) {
                #pragma unroll
                for (int j = 0; j < 8; ++j)
                    *reinterpret_cast<float4*>(&sm.A[rb + Pn + 4 * j]) =
                        *reinterpret_cast<const float4*>(&acc[4 * j]);
            } else {
                for (int c = 0; c <= idx; ++c) sm.A[rb + Pn + c] = acc[c];
            }
        }
        __syncthreads();

        // ---- Overlapped: solver {A(k+1); bar1; B(k+1)->LT[cur^1]} || C2(k) ----
        if (tid < 192) {
            if (tid < 32) phaseA(sm, k + 1, tid);
            asm volatile("bar.sync 1, 192;" ::: "memory");
            phaseB(sm, k + 1, cur ^ 1, tid);     // internal guard tid < 192-32k
        } else {
            phaseC2(sm, k, cur, tid - 192);
        }
        __syncthreads();
        cur ^= 1;
    }

    for (int j = tid; j < NPTS; j += K2T)
        out[(size_t)b * NPTS + j] = targets[(size_t)b * NPTS + j] - sm.u[j];
}

extern "C" void kernel_launch(void* const* d_in, const int* in_sizes, int n_in,
                              void* d_out, int out_size)
{
    const float* data    = (const float*)d_in[0];   // [32, 256, 128] f32
    const float* targets = (const float*)d_in[1];   // [32, 256]      f32
    float* out = (float*)d_out;                     // [32, 256]      f32

    gram_kernel<<<BATCH * 36, 256>>>(data);

    const size_t smem_bytes = sizeof(K2Smem);
    cudaFuncSetAttribute(chol_kernel,
                         cudaFuncAttributeMaxDynamicSharedMemorySize,
                         (int)smem_bytes);
    chol_kernel<<<BATCH, K2T, smem_bytes>>>(targets, out);
}